// round 12
// baseline (speedup 1.0000x reference)
#include <cuda_runtime.h>
#include <cuda_fp16.h>
#include <cstddef>
#include <cstdint>

// Problem constants
#define B_ 2
#define S_ 4096
#define D_ 512
#define H_ 8
#define DH_ 64
#define NP_ 256   // pairs per row (D_/2)

// ---------------- scratch (no allocation allowed) ----------------
__device__ __align__(16) uint32_t g_xh[(size_t)B_ * S_ * NP_];
__device__ __align__(16) uint32_t g_qh[(size_t)B_ * S_ * NP_];
__device__ __align__(16) uint32_t g_kh[(size_t)B_ * S_ * NP_];
__device__ __align__(16) uint32_t g_vh[(size_t)B_ * S_ * NP_];
__device__ __align__(16) uint32_t g_oh[(size_t)B_ * S_ * NP_];
// weights as k-pair-packed half: [4][256 kp][512 n] uint32
__device__ __align__(16) uint32_t g_wh[4][(size_t)NP_ * D_];

// ---------------- helpers ----------------
__device__ __forceinline__ uint32_t smem_u32(const void* p) {
    uint32_t a;
    asm("{ .reg .u64 t; cvta.to.shared.u64 t, %1; cvt.u32.u64 %0, t; }"
        : "=r"(a) : "l"(p));
    return a;
}
__device__ __forceinline__ uint32_t h2pack(float lo, float hi) {
    __half2 h = __floats2half2_rn(lo, hi);
    return *(uint32_t*)&h;
}
__device__ __forceinline__ uint32_t hmul2u(uint32_t a, __half2 s) {
    __half2 r = __hmul2(*(__half2*)&a, s);
    return *(uint32_t*)&r;
}
// exp2 on the MUFU pipe: 1 issue slot, ~2 ulp.
__device__ __forceinline__ float ex2a(float x) {
    float y;
    asm("ex2.approx.ftz.f32 %0, %1;" : "=f"(y) : "f"(x));
    return y;
}
// cp.async: 16B global->shared, L1-bypass (cg)
__device__ __forceinline__ void cp16(uint32_t smem_dst, const void* gptr) {
    asm volatile("cp.async.cg.shared.global [%0], [%1], 16;"
                 :: "r"(smem_dst), "l"(gptr) : "memory");
}
#define CP_COMMIT() asm volatile("cp.async.commit_group;" ::: "memory")
#define CP_WAIT(N)  asm volatile("cp.async.wait_group %0;" :: "n"(N) : "memory")

// fp16 MMA: D(16x8) += A(16x16) * B(16x8), fp32 accum
__device__ __forceinline__ void mma16(float* d, const uint32_t* a,
                                      uint32_t b0, uint32_t b1) {
    asm volatile(
        "mma.sync.aligned.m16n8k16.row.col.f32.f16.f16.f32 "
        "{%0,%1,%2,%3}, {%4,%5,%6,%7}, {%8,%9}, {%0,%1,%2,%3};"
        : "+f"(d[0]), "+f"(d[1]), "+f"(d[2]), "+f"(d[3])
        : "r"(a[0]), "r"(a[1]), "r"(a[2]), "r"(a[3]), "r"(b0), "r"(b1));
}

#define LDMX4(r0, r1, r2, r3, addr)                                        \
    asm volatile("ldmatrix.sync.aligned.m8n8.x4.shared.b16 "               \
                 "{%0,%1,%2,%3}, [%4];"                                    \
                 : "=r"(r0), "=r"(r1), "=r"(r2), "=r"(r3) : "r"(addr))
#define LDMX4T(r0, r1, r2, r3, addr)                                       \
    asm volatile("ldmatrix.sync.aligned.m8n8.x4.trans.shared.b16 "         \
                 "{%0,%1,%2,%3}, [%4];"                                    \
                 : "=r"(r0), "=r"(r1), "=r"(r2), "=r"(r3) : "r"(addr))

// ================= x -> half pairs =================
__global__ void __launch_bounds__(256)
cvt_x(const float4* __restrict__ x, uint4* __restrict__ xh)
{
    size_t i = (size_t)blockIdx.x * 256 + threadIdx.x;
    float4 a = x[2 * i], b = x[2 * i + 1];
    uint4 o;
    o.x = h2pack(a.x, a.y); o.y = h2pack(a.z, a.w);
    o.z = h2pack(b.x, b.y); o.w = h2pack(b.z, b.w);
    xh[i] = o;
}

// ================= W -> k-pair-packed half =================
__global__ void __launch_bounds__(256)
cvt_w(const float* __restrict__ Wq, const float* __restrict__ Wk,
      const float* __restrict__ Wv, const float* __restrict__ Wo,
      uint32_t* __restrict__ Whg)
{
    const float* W;
    if (blockIdx.y == 0)      W = Wq;
    else if (blockIdx.y == 1) W = Wk;
    else if (blockIdx.y == 2) W = Wv;
    else                      W = Wo;
    size_t i = (size_t)blockIdx.x * 256 + threadIdx.x;  // kp*512 + n
    size_t kp = i >> 9, n = i & 511;
    float lo = W[(2 * kp) * D_ + n];
    float hi = W[(2 * kp + 1) * D_ + n];
    Whg[(size_t)blockIdx.y * NP_ * D_ + i] = h2pack(lo, hi);
}

// ================= fp16 GEMM: C = relu(Ah[M,512] @ W[512,512] + b) =========
// Block 128m x 128n, k-tile 32 (16 kp). 8 warps 2m x 4n, warp tile 64m x 32n.
// cp.async double-buffered staging (no prefetch registers).
#define GA_STR 20
#define GW_STR 136
#define GAB (128 * GA_STR)    // uint32 per A buffer
#define GWB (16 * GW_STR)     // uint32 per W buffer

template <int OUT_HALF>
__device__ __forceinline__ void gemm_h_body(
    const uint32_t* __restrict__ Ah_g,
    const uint32_t* __restrict__ Wh_g,
    const float* __restrict__ bias,
    void* __restrict__ Cout,
    int bm, int bn)
{
    __shared__ __align__(16) uint32_t Ah[2][GAB];
    __shared__ __align__(16) uint32_t Wh[2][GWB];

    const int tid = threadIdx.x;
    const int lane = tid & 31;
    const int wid = tid >> 5;
    const int wm = wid >> 2;
    const int wn = wid & 3;
    const int g = lane >> 2;
    const int c = lane & 3;

    const uint32_t ah0 = smem_u32(&Ah[0][0]);
    const uint32_t wh0 = smem_u32(&Wh[0][0]);

    float acc[4][4][4];
    #pragma unroll
    for (int mt = 0; mt < 4; mt++)
        #pragma unroll
        for (int nt = 0; nt < 4; nt++)
            #pragma unroll
            for (int j = 0; j < 4; j++) acc[mt][nt][j] = 0.0f;

    // ---- prologue: cp tile 0 into buf 0
    #pragma unroll
    for (int i = 0; i < 2; i++) {
        int cid = 2 * tid + i;
        int m = cid >> 2, ch = cid & 3;
        cp16(ah0 + (m * GA_STR + 4 * ch) * 4,
             Ah_g + (size_t)(bm + m) * NP_ + 4 * ch);
        int kp = cid >> 5, n4 = cid & 31;
        cp16(wh0 + (kp * GW_STR + 4 * n4) * 4,
             Wh_g + (size_t)kp * D_ + bn + 4 * n4);
    }
    CP_COMMIT();

    for (int kt = 0; kt < 16; kt++) {
        __syncthreads();   // prior compute on the buffer we are about to fill
        if (kt < 15) {
            const int nb = (kt + 1) & 1;
            #pragma unroll
            for (int i = 0; i < 2; i++) {
                int cid = 2 * tid + i;
                int m = cid >> 2, ch = cid & 3;
                cp16(ah0 + (nb * GAB + m * GA_STR + 4 * ch) * 4,
                     Ah_g + (size_t)(bm + m) * NP_ + (kt + 1) * 16 + 4 * ch);
                int kp = cid >> 5, n4 = cid & 31;
                cp16(wh0 + (nb * GWB + kp * GW_STR + 4 * n4) * 4,
                     Wh_g + (size_t)((kt + 1) * 16 + kp) * D_ + bn + 4 * n4);
            }
            CP_COMMIT();
            CP_WAIT(1);    // tile kt resident; kt+1 in flight
        } else {
            CP_WAIT(0);
        }
        __syncthreads();

        const uint32_t* Ab = &Ah[kt & 1][0];
        const uint32_t* Wb = &Wh[kt & 1][0];

        #pragma unroll
        for (int kc = 0; kc < 2; kc++) {
            uint32_t af[4][4];
            #pragma unroll
            for (int mt = 0; mt < 4; mt++) {
                int base = (wm * 64 + mt * 16 + g) * GA_STR + kc * 8 + c;
                af[mt][0] = Ab[base];
                af[mt][1] = Ab[base + 8 * GA_STR];
                af[mt][2] = Ab[base + 4];
                af[mt][3] = Ab[base + 8 * GA_STR + 4];
            }
            #pragma unroll
            for (int nt = 0; nt < 4; nt++) {
                int rb = (kc * 8 + c) * GW_STR + wn * 32 + nt * 8 + g;
                uint32_t b0 = Wb[rb];
                uint32_t b1 = Wb[rb + 4 * GW_STR];
                #pragma unroll
                for (int mt = 0; mt < 4; mt++)
                    mma16(acc[mt][nt], af[mt], b0, b1);
            }
        }
    }

    #pragma unroll
    for (int mt = 0; mt < 4; mt++) {
        const int row = bm + wm * 64 + mt * 16 + g;
        #pragma unroll
        for (int nt = 0; nt < 4; nt++) {
            const int col = bn + wn * 32 + nt * 8 + 2 * c;
            const float b0 = bias[col], b1 = bias[col + 1];
            float v00 = fmaxf(acc[mt][nt][0] + b0, 0.0f);
            float v01 = fmaxf(acc[mt][nt][1] + b1, 0.0f);
            float v10 = fmaxf(acc[mt][nt][2] + b0, 0.0f);
            float v11 = fmaxf(acc[mt][nt][3] + b1, 0.0f);
            if (OUT_HALF) {
                uint32_t* Ch = (uint32_t*)Cout;
                Ch[(size_t)row * NP_ + (col >> 1)]       = h2pack(v00, v01);
                Ch[(size_t)(row + 8) * NP_ + (col >> 1)] = h2pack(v10, v11);
            } else {
                float* Cf = (float*)Cout;
                float2 a; a.x = v00; a.y = v01;
                float2 bb; bb.x = v10; bb.y = v11;
                *(float2*)(Cf + (size_t)row * D_ + col) = a;
                *(float2*)(Cf + (size_t)(row + 8) * D_ + col) = bb;
            }
        }
    }
}

__global__ void __launch_bounds__(256, 2)
gemm_h_qkv(const uint32_t* __restrict__ xh, const uint32_t* __restrict__ Whg,
           const float* __restrict__ bq, uint32_t* __restrict__ Q,
           const float* __restrict__ bk, uint32_t* __restrict__ K,
           const float* __restrict__ bv, uint32_t* __restrict__ V)
{
    const float* bias; uint32_t* C;
    if (blockIdx.z == 0)      { bias = bq; C = Q; }
    else if (blockIdx.z == 1) { bias = bk; C = K; }
    else                      { bias = bv; C = V; }
    gemm_h_body<1>(xh, Whg + (size_t)blockIdx.z * NP_ * D_, bias, C,
                   blockIdx.y * 128, blockIdx.x * 128);
}

__global__ void __launch_bounds__(256, 2)
gemm_h_out(const uint32_t* __restrict__ Ah, const uint32_t* __restrict__ Whg,
           const float* __restrict__ bias, float* __restrict__ C)
{
    gemm_h_body<0>(Ah, Whg + (size_t)3 * NP_ * D_, bias, C,
                   blockIdx.y * 128, blockIdx.x * 128);
}

// ================= flash attention: 16m tiles + cp.async double buffer =====
// BM=64 q rows, BN=64 keys/tile, 128 threads (4 warps, 16m x 64n each).
#define AT_BM 64
#define HSTR 36
#define KVBUF (64 * HSTR)           // uint32 per K or V buffer
#define KVBUF_BYTES (KVBUF * 4)     // 9216 B

__global__ void __launch_bounds__(128, 4)
attn_h(const uint32_t* __restrict__ Qg, const uint32_t* __restrict__ Kg,
       const uint32_t* __restrict__ Vg, uint32_t* __restrict__ Og)
{
    __shared__ __align__(16) uint32_t Qs[AT_BM * HSTR];
    __shared__ __align__(16) uint32_t Ks[2][KVBUF];
    __shared__ __align__(16) uint32_t Vs[2][KVBUF];

    const int tid = threadIdx.x;
    const int lane = tid & 31;
    const int wid = tid >> 5;
    const int g = lane >> 2;   // 0..7
    const int c = lane & 3;    // 0..3
    const int qblk = blockIdx.x;
    const int h = blockIdx.y;
    const int b = blockIdx.z;

    const __half2 sc2 = __float2half2_rn(0.18033688f);  // (1/8)*log2(e)

    const size_t kvrow0 = (size_t)b * S_;
    const uint32_t ks0 = smem_u32(&Ks[0][0]);
    const uint32_t vs0 = smem_u32(&Vs[0][0]);

    const int sn0 = tid >> 3;        // key row for it=0 (0..15)
    const int sch = tid & 7;         // 16B chunk within row

    // ---- prefetch tile 0 (buf 0) via cp.async, before Q staging
    {
        #pragma unroll
        for (int it = 0; it < 4; it++) {
            int n = sn0 + it * 16;
            size_t goff = (kvrow0 + n) * NP_ + h * 32 + 4 * sch;
            uint32_t so = (uint32_t)((n * HSTR + 4 * sch) * 4);
            cp16(ks0 + so, Kg + goff);
            cp16(vs0 + so, Vg + goff);
        }
        CP_COMMIT();
    }

    // ---- stage Q (copy + scale)
    const size_t qrow0 = (size_t)b * S_ + qblk * AT_BM;
    #pragma unroll
    for (int it = 0; it < 4; it++) {
        int idx = tid + it * 128;
        int m = idx >> 3, ch = idx & 7;
        uint4 u = *(const uint4*)(Qg + (qrow0 + m) * NP_ + h * 32 + 4 * ch);
        u.x = hmul2u(u.x, sc2); u.y = hmul2u(u.y, sc2);
        u.z = hmul2u(u.z, sc2); u.w = hmul2u(u.w, sc2);
        *(uint4*)&Qs[m * HSTR + 4 * ch] = u;
    }
    __syncthreads();

    // Q a-frags to registers (4 k-chunks of 16 d)
    uint32_t qf[4][4];
    {
        const int r0 = (wid * 16 + g) * HSTR;
        const int r1 = r0 + 8 * HSTR;
        #pragma unroll
        for (int kc = 0; kc < 4; kc++) {
            qf[kc][0] = Qs[r0 + 8 * kc + c];
            qf[kc][1] = Qs[r1 + 8 * kc + c];
            qf[kc][2] = Qs[r0 + 8 * kc + 4 + c];
            qf[kc][3] = Qs[r1 + 8 * kc + 4 + c];
        }
    }

    // ldmatrix per-thread fragment offsets (within a buffer)
    const int j = lane >> 3, r = lane & 7;
    const uint32_t kfrag = ((((j >> 1) * 8 + r) * HSTR + (j & 1) * 4) << 2);
    const uint32_t vfrag = ((((j & 1) * 8 + r) * HSTR + (j >> 1) * 4) << 2);

    float o[8][4];
    #pragma unroll
    for (int nt = 0; nt < 8; nt++)
        #pragma unroll
        for (int jj = 0; jj < 4; jj++) o[nt][jj] = 0.0f;
    float m0 = -1e30f, m1 = -1e30f, l0 = 0.0f, l1 = 0.0f;

    const int NTILES = S_ / 64;
    for (int tile = 0; tile < NTILES; tile++) {
        __syncthreads();
        if (tile + 1 < NTILES) {
            const int nb = (tile + 1) & 1;
            const int t1 = (tile + 1) * 64;
            #pragma unroll
            for (int it = 0; it < 4; it++) {
                int n = sn0 + it * 16;
                size_t goff = (kvrow0 + t1 + n) * NP_ + h * 32 + 4 * sch;
                uint32_t so = (uint32_t)(nb * KVBUF_BYTES + (n * HSTR + 4 * sch) * 4);
                cp16(ks0 + so, Kg + goff);
                cp16(vs0 + so, Vg + goff);
            }
            CP_COMMIT();
            CP_WAIT(1);
        } else {
            CP_WAIT(0);
        }
        __syncthreads();

        const uint32_t kbase = ks0 + (tile & 1) * KVBUF_BYTES + kfrag;
        const uint32_t vbase = vs0 + (tile & 1) * KVBUF_BYTES + vfrag;

        // ---- S = Q @ K^T
        float sacc[8][4];
        #pragma unroll
        for (int nt = 0; nt < 8; nt++)
            #pragma unroll
            for (int jj = 0; jj < 4; jj++) sacc[nt][jj] = 0.0f;

        #pragma unroll
        for (int kc = 0; kc < 4; kc++) {
            #pragma unroll
            for (int np = 0; np < 4; np++) {
                uint32_t r0, r1, r2, r3;
                LDMX4(r0, r1, r2, r3, kbase + np * (16 * HSTR * 4) + kc * 32);
                mma16(sacc[2 * np],     qf[kc], r0, r1);
                mma16(sacc[2 * np + 1], qf[kc], r2, r3);
            }
        }

        // ---- online softmax (log2 domain), exp on MUFU
        float tm0 = -1e30f, tm1 = -1e30f;
        #pragma unroll
        for (int nt = 0; nt < 8; nt++) {
            tm0 = fmaxf(tm0, fmaxf(sacc[nt][0], sacc[nt][1]));
            tm1 = fmaxf(tm1, fmaxf(sacc[nt][2], sacc[nt][3]));
        }
        tm0 = fmaxf(tm0, __shfl_xor_sync(0xffffffff, tm0, 1));
        tm0 = fmaxf(tm0, __shfl_xor_sync(0xffffffff, tm0, 2));
        tm1 = fmaxf(tm1, __shfl_xor_sync(0xffffffff, tm1, 1));
        tm1 = fmaxf(tm1, __shfl_xor_sync(0xffffffff, tm1, 2));

        // skip the rescale when no row in the warp updated its max (~40% of tiles)
        if (__any_sync(0xffffffff, (tm0 > m0) | (tm1 > m1))) {
            float mn0 = fmaxf(m0, tm0), mn1 = fmaxf(m1, tm1);
            float corr0 = ex2a(m0 - mn0), corr1 = ex2a(m1 - mn1);
            m0 = mn0; m1 = mn1;
            l0 *= corr0; l1 *= corr1;
            #pragma unroll
            for (int nt = 0; nt < 8; nt++) {
                o[nt][0] *= corr0; o[nt][1] *= corr0;
                o[nt][2] *= corr1; o[nt][3] *= corr1;
            }
        }

        float rs0 = 0.0f, rs1 = 0.0f;
        #pragma unroll
        for (int nt = 0; nt < 8; nt++) {
            sacc[nt][0] = ex2a(sacc[nt][0] - m0);
            sacc[nt][1] = ex2a(sacc[nt][1] - m0);
            sacc[nt][2] = ex2a(sacc[nt][2] - m1);
            sacc[nt][3] = ex2a(sacc[nt][3] - m1);
            rs0 += sacc[nt][0] + sacc[nt][1];
            rs1 += sacc[nt][2] + sacc[nt][3];
        }
        rs0 += __shfl_xor_sync(0xffffffff, rs0, 1);
        rs0 += __shfl_xor_sync(0xffffffff, rs0, 2);
        rs1 += __shfl_xor_sync(0xffffffff, rs1, 1);
        rs1 += __shfl_xor_sync(0xffffffff, rs1, 2);
        l0 += rs0;
        l1 += rs1;

        // ---- O += P @ V via ldmatrix.trans
        #pragma unroll
        for (int kc = 0; kc < 4; kc++) {
            uint32_t af[4];
            af[0] = h2pack(sacc[2 * kc][0], sacc[2 * kc][1]);
            af[1] = h2pack(sacc[2 * kc][2], sacc[2 * kc][3]);
            af[2] = h2pack(sacc[2 * kc + 1][0], sacc[2 * kc + 1][1]);
            af[3] = h2pack(sacc[2 * kc + 1][2], sacc[2 * kc + 1][3]);
            #pragma unroll
            for (int np = 0; np < 4; np++) {
                uint32_t r0, r1, r2, r3;
                LDMX4T(r0, r1, r2, r3, vbase + kc * (16 * HSTR * 4) + np * 32);
                mma16(o[2 * np],     af, r0, r1);
                mma16(o[2 * np + 1], af, r2, r3);
            }
        }
    }

    // ---- epilogue: half output pairs
    const float inv0 = 1.0f / l0, inv1 = 1.0f / l1;
    uint32_t* ob = Og + (qrow0 + wid * 16 + g) * NP_ + h * 32;
    #pragma unroll
    for (int nt = 0; nt < 8; nt++) {
        ob[nt * 4 + c]            = h2pack(o[nt][0] * inv0, o[nt][1] * inv0);
        ob[8 * NP_ + nt * 4 + c]  = h2pack(o[nt][2] * inv1, o[nt][3] * inv1);
    }
}

// ---------------- launch ----------------
extern "C" void kernel_launch(void* const* d_in, const int* in_sizes, int n_in,
                              void* d_out, int out_size)
{
    const float* x  = (const float*)d_in[0];
    const float* Wq = (const float*)d_in[1];
    const float* bq = (const float*)d_in[2];
    const float* Wk = (const float*)d_in[3];
    const float* bk = (const float*)d_in[4];
    const float* Wv = (const float*)d_in[5];
    const float* bv = (const float*)d_in[6];
    const float* Wo = (const float*)d_in[7];
    const float* bo = (const float*)d_in[8];
    float* out = (float*)d_out;

    uint32_t *xh, *Qh, *Kh, *Vh, *Oh, *Whg;
    cudaGetSymbolAddress((void**)&xh, g_xh);
    cudaGetSymbolAddress((void**)&Qh, g_qh);
    cudaGetSymbolAddress((void**)&Kh, g_kh);
    cudaGetSymbolAddress((void**)&Vh, g_vh);
    cudaGetSymbolAddress((void**)&Oh, g_oh);
    cudaGetSymbolAddress((void**)&Whg, g_wh);

    cvt_x<<<2048, 256>>>((const float4*)x, (uint4*)xh);
    dim3 wgrid(512, 4);
    cvt_w<<<wgrid, 256>>>(Wq, Wk, Wv, Wo, Whg);

    dim3 qkv_grid(D_ / 128, (B_ * S_) / 128, 3);   // (4, 64, 3)
    gemm_h_qkv<<<qkv_grid, 256>>>(xh, Whg, bq, Qh, bk, Kh, bv, Vh);

    dim3 agrid(S_ / AT_BM, H_, B_);  // (64, 8, 2) = 1024 blocks
    attn_h<<<agrid, 128>>>(Qh, Kh, Vh, Oh);

    dim3 ogrid(D_ / 128, (B_ * S_) / 128);         // (4, 64)
    gemm_h_out<<<ogrid, 256>>>(Oh, Whg, bo, out);
}

// round 13
// speedup vs baseline: 1.0192x; 1.0192x over previous
#include <cuda_runtime.h>
#include <cuda_fp16.h>
#include <cstddef>
#include <cstdint>

// Problem constants
#define B_ 2
#define S_ 4096
#define D_ 512
#define H_ 8
#define DH_ 64
#define NP_ 256   // pairs per row (D_/2)

// ---------------- scratch (no allocation allowed) ----------------
__device__ __align__(16) uint32_t g_xh[(size_t)B_ * S_ * NP_];
__device__ __align__(16) uint32_t g_qh[(size_t)B_ * S_ * NP_];
__device__ __align__(16) uint32_t g_kh[(size_t)B_ * S_ * NP_];
__device__ __align__(16) uint32_t g_vh[(size_t)B_ * S_ * NP_];
__device__ __align__(16) uint32_t g_oh[(size_t)B_ * S_ * NP_];
// weights TRANSPOSED, k-pair-packed half: [4][512 n][256 kp] uint32
__device__ __align__(16) uint32_t g_wh[4][(size_t)D_ * NP_];

// ---------------- helpers ----------------
__device__ __forceinline__ uint32_t smem_u32(const void* p) {
    uint32_t a;
    asm("{ .reg .u64 t; cvta.to.shared.u64 t, %1; cvt.u32.u64 %0, t; }"
        : "=r"(a) : "l"(p));
    return a;
}
__device__ __forceinline__ uint32_t h2pack(float lo, float hi) {
    __half2 h = __floats2half2_rn(lo, hi);
    return *(uint32_t*)&h;
}
__device__ __forceinline__ uint32_t hmul2u(uint32_t a, __half2 s) {
    __half2 r = __hmul2(*(__half2*)&a, s);
    return *(uint32_t*)&r;
}
// exp2 on the MUFU pipe: 1 issue slot, ~2 ulp.
__device__ __forceinline__ float ex2a(float x) {
    float y;
    asm("ex2.approx.ftz.f32 %0, %1;" : "=f"(y) : "f"(x));
    return y;
}
// cp.async: 16B global->shared, L1-bypass (cg)
__device__ __forceinline__ void cp16(uint32_t smem_dst, const void* gptr) {
    asm volatile("cp.async.cg.shared.global [%0], [%1], 16;"
                 :: "r"(smem_dst), "l"(gptr) : "memory");
}
#define CP_COMMIT() asm volatile("cp.async.commit_group;" ::: "memory")
#define CP_WAIT(N)  asm volatile("cp.async.wait_group %0;" :: "n"(N) : "memory")

// fp16 MMA: D(16x8) += A(16x16) * B(16x8), fp32 accum
__device__ __forceinline__ void mma16(float* d, const uint32_t* a,
                                      uint32_t b0, uint32_t b1) {
    asm volatile(
        "mma.sync.aligned.m16n8k16.row.col.f32.f16.f16.f32 "
        "{%0,%1,%2,%3}, {%4,%5,%6,%7}, {%8,%9}, {%0,%1,%2,%3};"
        : "+f"(d[0]), "+f"(d[1]), "+f"(d[2]), "+f"(d[3])
        : "r"(a[0]), "r"(a[1]), "r"(a[2]), "r"(a[3]), "r"(b0), "r"(b1));
}

#define LDMX4(r0, r1, r2, r3, addr)                                        \
    asm volatile("ldmatrix.sync.aligned.m8n8.x4.shared.b16 "               \
                 "{%0,%1,%2,%3}, [%4];"                                    \
                 : "=r"(r0), "=r"(r1), "=r"(r2), "=r"(r3) : "r"(addr))
#define LDMX4T(r0, r1, r2, r3, addr)                                       \
    asm volatile("ldmatrix.sync.aligned.m8n8.x4.trans.shared.b16 "         \
                 "{%0,%1,%2,%3}, [%4];"                                    \
                 : "=r"(r0), "=r"(r1), "=r"(r2), "=r"(r3) : "r"(addr))
#define LDMX2T(r0, r1, addr)                                               \
    asm volatile("ldmatrix.sync.aligned.m8n8.x2.trans.shared.b16 "         \
                 "{%0,%1}, [%2];"                                          \
                 : "=r"(r0), "=r"(r1) : "r"(addr))

// ================= x -> half pairs =================
__global__ void __launch_bounds__(256)
cvt_x(const float4* __restrict__ x, uint4* __restrict__ xh)
{
    size_t i = (size_t)blockIdx.x * 256 + threadIdx.x;
    float4 a = x[2 * i], b = x[2 * i + 1];
    uint4 o;
    o.x = h2pack(a.x, a.y); o.y = h2pack(a.z, a.w);
    o.z = h2pack(b.x, b.y); o.w = h2pack(b.z, b.w);
    xh[i] = o;
}

// ================= W -> transposed k-pair-packed half ======================
// Whn[z][n][kp] = (W[2kp][n], W[2kp+1][n]); tiled transpose, coalesced both sides.
__global__ void __launch_bounds__(256)
cvt_wn(const float* __restrict__ Wq, const float* __restrict__ Wk,
       const float* __restrict__ Wv, const float* __restrict__ Wo,
       uint32_t* __restrict__ Whn)
{
    __shared__ uint32_t t[32][33];
    const float* W;
    if (blockIdx.z == 0)      W = Wq;
    else if (blockIdx.z == 1) W = Wk;
    else if (blockIdx.z == 2) W = Wv;
    else                      W = Wo;
    const int tx = threadIdx.x, ty = threadIdx.y;
    const int kp0 = blockIdx.x * 32, n0 = blockIdx.y * 32;
    #pragma unroll
    for (int i = 0; i < 4; i++) {
        int kp = kp0 + ty + i * 8;
        t[ty + i * 8][tx] = h2pack(W[(size_t)(2 * kp) * D_ + n0 + tx],
                                   W[(size_t)(2 * kp + 1) * D_ + n0 + tx]);
    }
    __syncthreads();
    uint32_t* dst = Whn + (size_t)blockIdx.z * D_ * NP_;
    #pragma unroll
    for (int i = 0; i < 4; i++) {
        int n = n0 + ty + i * 8;
        dst[(size_t)n * NP_ + kp0 + tx] = t[tx][ty + i * 8];
    }
}

// ================= fp16 GEMM: C = relu(Ah[M,512] @ W + b) ==================
// Block 128m x 128n, k-tile 32 (16 kp). 8 warps 2m x 4n, warp tile 64m x 32n.
// cp.async double buffer; A and B fragments via ldmatrix (stride 20: CF).
#define GA_STR 20
#define GAB (128 * GA_STR)    // uint32 per A buffer (== W buffer)

template <int OUT_HALF>
__device__ __forceinline__ void gemm_h_body(
    const uint32_t* __restrict__ Ah_g,    // [M][256] half k-pairs
    const uint32_t* __restrict__ Wn_g,    // [512 n][256 kp] half k-pairs
    const float* __restrict__ bias,
    void* __restrict__ Cout,
    int bm, int bn)
{
    __shared__ __align__(16) uint32_t Ah[2][GAB];
    __shared__ __align__(16) uint32_t Wn[2][GAB];

    const int tid = threadIdx.x;
    const int lane = tid & 31;
    const int wid = tid >> 5;
    const int wm = wid >> 2;
    const int wn = wid & 3;
    const int g = lane >> 2;
    const int c = lane & 3;

    const uint32_t ah0 = smem_u32(&Ah[0][0]);
    const uint32_t wn0 = smem_u32(&Wn[0][0]);

    // ldmatrix per-thread fragment offsets (bytes, within a buffer)
    const int j = lane >> 3, r = lane & 7;
    const uint32_t afrag = (((j & 1) * 8 + r) * GA_STR + (j >> 1) * 4) * 4;   // A (non-trans A-frag)
    const uint32_t wfrag = (((j >> 1) * 8 + r) * GA_STR + (j & 1) * 4) * 4;   // B (non-trans B-frag)

    float acc[4][4][4];
    #pragma unroll
    for (int mt = 0; mt < 4; mt++)
        #pragma unroll
        for (int nt = 0; nt < 4; nt++)
            #pragma unroll
            for (int jj = 0; jj < 4; jj++) acc[mt][nt][jj] = 0.0f;

    // ---- prologue: cp tile 0 into buf 0 (A: 128m x 16kp; W: 128n x 16kp)
    #pragma unroll
    for (int i = 0; i < 2; i++) {
        int cid = 2 * tid + i;
        int m = cid >> 2, ch = cid & 3;
        cp16(ah0 + (m * GA_STR + 4 * ch) * 4,
             Ah_g + (size_t)(bm + m) * NP_ + 4 * ch);
        cp16(wn0 + (m * GA_STR + 4 * ch) * 4,
             Wn_g + (size_t)(bn + m) * NP_ + 4 * ch);
    }
    CP_COMMIT();

    for (int kt = 0; kt < 16; kt++) {
        __syncthreads();
        if (kt < 15) {
            const int nb = (kt + 1) & 1;
            #pragma unroll
            for (int i = 0; i < 2; i++) {
                int cid = 2 * tid + i;
                int m = cid >> 2, ch = cid & 3;
                cp16(ah0 + (nb * GAB + m * GA_STR + 4 * ch) * 4,
                     Ah_g + (size_t)(bm + m) * NP_ + (kt + 1) * 16 + 4 * ch);
                cp16(wn0 + (nb * GAB + m * GA_STR + 4 * ch) * 4,
                     Wn_g + (size_t)(bn + m) * NP_ + (kt + 1) * 16 + 4 * ch);
            }
            CP_COMMIT();
            CP_WAIT(1);
        } else {
            CP_WAIT(0);
        }
        __syncthreads();

        const uint32_t a_ld = ah0 + (kt & 1) * (GAB * 4) + afrag;
        const uint32_t w_ld = wn0 + (kt & 1) * (GAB * 4) + wfrag;

        #pragma unroll
        for (int kc = 0; kc < 2; kc++) {
            uint32_t af[4][4];
            #pragma unroll
            for (int mt = 0; mt < 4; mt++)
                LDMX4(af[mt][0], af[mt][1], af[mt][2], af[mt][3],
                      a_ld + (wm * 64 + mt * 16) * (GA_STR * 4) + kc * 32);
            #pragma unroll
            for (int ntb = 0; ntb < 2; ntb++) {
                uint32_t b0, b1, b2, b3;
                LDMX4(b0, b1, b2, b3,
                      w_ld + (wn * 32 + ntb * 16) * (GA_STR * 4) + kc * 32);
                #pragma unroll
                for (int mt = 0; mt < 4; mt++) {
                    mma16(acc[mt][2 * ntb],     af[mt], b0, b1);
                    mma16(acc[mt][2 * ntb + 1], af[mt], b2, b3);
                }
            }
        }
    }

    #pragma unroll
    for (int mt = 0; mt < 4; mt++) {
        const int row = bm + wm * 64 + mt * 16 + g;
        #pragma unroll
        for (int nt = 0; nt < 4; nt++) {
            const int col = bn + wn * 32 + nt * 8 + 2 * c;
            const float b0 = bias[col], b1 = bias[col + 1];
            float v00 = fmaxf(acc[mt][nt][0] + b0, 0.0f);
            float v01 = fmaxf(acc[mt][nt][1] + b1, 0.0f);
            float v10 = fmaxf(acc[mt][nt][2] + b0, 0.0f);
            float v11 = fmaxf(acc[mt][nt][3] + b1, 0.0f);
            if (OUT_HALF) {
                uint32_t* Ch = (uint32_t*)Cout;
                Ch[(size_t)row * NP_ + (col >> 1)]       = h2pack(v00, v01);
                Ch[(size_t)(row + 8) * NP_ + (col >> 1)] = h2pack(v10, v11);
            } else {
                float* Cf = (float*)Cout;
                float2 a; a.x = v00; a.y = v01;
                float2 bb; bb.x = v10; bb.y = v11;
                *(float2*)(Cf + (size_t)row * D_ + col) = a;
                *(float2*)(Cf + (size_t)(row + 8) * D_ + col) = bb;
            }
        }
    }
}

__global__ void __launch_bounds__(256, 2)
gemm_h_qkv(const uint32_t* __restrict__ xh, const uint32_t* __restrict__ Whn,
           const float* __restrict__ bq, uint32_t* __restrict__ Q,
           const float* __restrict__ bk, uint32_t* __restrict__ K,
           const float* __restrict__ bv, uint32_t* __restrict__ V)
{
    const float* bias; uint32_t* C;
    if (blockIdx.z == 0)      { bias = bq; C = Q; }
    else if (blockIdx.z == 1) { bias = bk; C = K; }
    else                      { bias = bv; C = V; }
    gemm_h_body<1>(xh, Whn + (size_t)blockIdx.z * D_ * NP_, bias, C,
                   blockIdx.y * 128, blockIdx.x * 128);
}

__global__ void __launch_bounds__(256, 2)
gemm_h_out(const uint32_t* __restrict__ Ah, const uint32_t* __restrict__ Whn,
           const float* __restrict__ bias, float* __restrict__ C)
{
    gemm_h_body<0>(Ah, Whn + (size_t)3 * D_ * NP_, bias, C,
                   blockIdx.y * 128, blockIdx.x * 128);
}

// ================= flash attention: ones-column l, cp.async double buffer ===
// BM=64 q rows, BN=64 keys/tile, 128 threads (4 warps, 16m x 64n each).
// V pairs 32-35 hold a ones-column (d=64 -> 1.0): PV's extra n-octet
// accumulates the softmax denominator with rescaling applied automatically.
#define AT_BM 64
#define HSTR 36
#define KVBUF (64 * HSTR)           // uint32 per K or V buffer
#define KVBUF_BYTES (KVBUF * 4)     // 9216 B

__global__ void __launch_bounds__(128, 4)
attn_h(const uint32_t* __restrict__ Qg, const uint32_t* __restrict__ Kg,
       const uint32_t* __restrict__ Vg, uint32_t* __restrict__ Og)
{
    __shared__ __align__(16) uint32_t Qs[AT_BM * HSTR];
    __shared__ __align__(16) uint32_t Ks[2][KVBUF];
    __shared__ __align__(16) uint32_t Vs[2][KVBUF];

    const int tid = threadIdx.x;
    const int lane = tid & 31;
    const int wid = tid >> 5;
    const int g = lane >> 2;   // 0..7
    const int c = lane & 3;    // 0..3
    const int qblk = blockIdx.x;
    const int h = blockIdx.y;
    const int b = blockIdx.z;

    const __half2 sc2 = __float2half2_rn(0.18033688f);  // (1/8)*log2(e)

    const size_t kvrow0 = (size_t)b * S_;
    const uint32_t ks0 = smem_u32(&Ks[0][0]);
    const uint32_t vs0 = smem_u32(&Vs[0][0]);

    const int sn0 = tid >> 3;        // key row for it=0 (0..15)
    const int sch = tid & 7;         // 16B chunk within row

    // ---- prefetch tile 0 (buf 0) via cp.async
    {
        #pragma unroll
        for (int it = 0; it < 4; it++) {
            int n = sn0 + it * 16;
            size_t goff = (kvrow0 + n) * NP_ + h * 32 + 4 * sch;
            uint32_t so = (uint32_t)((n * HSTR + 4 * sch) * 4);
            cp16(ks0 + so, Kg + goff);
            cp16(vs0 + so, Vg + goff);
        }
        CP_COMMIT();
    }

    // ---- init ones-column in V pads (pairs 32-35), both buffers, ONCE.
    // cp.async never touches words 32-35 of a row, so this persists.
    {
        int buf = tid >> 6, n = tid & 63;   // 128 threads cover 2 x 64 rows
        uint4 ones = make_uint4(0x3C00u, 0u, 0u, 0u);  // d64=1.0, d65..71=0
        *(uint4*)&Vs[buf][n * HSTR + 32] = ones;
    }

    // ---- stage Q (copy + scale)
    const size_t qrow0 = (size_t)b * S_ + qblk * AT_BM;
    #pragma unroll
    for (int it = 0; it < 4; it++) {
        int idx = tid + it * 128;
        int m = idx >> 3, ch = idx & 7;
        uint4 u = *(const uint4*)(Qg + (qrow0 + m) * NP_ + h * 32 + 4 * ch);
        u.x = hmul2u(u.x, sc2); u.y = hmul2u(u.y, sc2);
        u.z = hmul2u(u.z, sc2); u.w = hmul2u(u.w, sc2);
        *(uint4*)&Qs[m * HSTR + 4 * ch] = u;
    }
    __syncthreads();

    // Q a-frags to registers (4 k-chunks of 16 d)
    uint32_t qf[4][4];
    {
        const int r0 = (wid * 16 + g) * HSTR;
        const int r1 = r0 + 8 * HSTR;
        #pragma unroll
        for (int kc = 0; kc < 4; kc++) {
            qf[kc][0] = Qs[r0 + 8 * kc + c];
            qf[kc][1] = Qs[r1 + 8 * kc + c];
            qf[kc][2] = Qs[r0 + 8 * kc + 4 + c];
            qf[kc][3] = Qs[r1 + 8 * kc + 4 + c];
        }
    }

    // ldmatrix per-thread fragment offsets (within a buffer)
    const int j = lane >> 3, r = lane & 7;
    const uint32_t kfrag = ((((j >> 1) * 8 + r) * HSTR + (j & 1) * 4) << 2);
    const uint32_t vfrag = ((((j & 1) * 8 + r) * HSTR + (j >> 1) * 4) << 2);
    // x2 ones-column frag: lanes 0-7 rows r, 8-15 rows 8+r, at word 32
    const int rr = ((lane >> 3) & 1) * 8 + (lane & 7);
    const uint32_t vfrag2 = (uint32_t)((rr * HSTR + 32) << 2);

    float o[8][4];
    #pragma unroll
    for (int nt = 0; nt < 8; nt++)
        #pragma unroll
        for (int jj = 0; jj < 4; jj++) o[nt][jj] = 0.0f;
    float oex[4] = {0.0f, 0.0f, 0.0f, 0.0f};   // ones-column accum (l in col 64)
    float m0 = -1e30f, m1 = -1e30f;

    const int NTILES = S_ / 64;
    for (int tile = 0; tile < NTILES; tile++) {
        __syncthreads();
        if (tile + 1 < NTILES) {
            const int nb = (tile + 1) & 1;
            const int t1 = (tile + 1) * 64;
            #pragma unroll
            for (int it = 0; it < 4; it++) {
                int n = sn0 + it * 16;
                size_t goff = (kvrow0 + t1 + n) * NP_ + h * 32 + 4 * sch;
                uint32_t so = (uint32_t)(nb * KVBUF_BYTES + (n * HSTR + 4 * sch) * 4);
                cp16(ks0 + so, Kg + goff);
                cp16(vs0 + so, Vg + goff);
            }
            CP_COMMIT();
            CP_WAIT(1);
        } else {
            CP_WAIT(0);
        }
        __syncthreads();

        const uint32_t kbase = ks0 + (tile & 1) * KVBUF_BYTES + kfrag;
        const uint32_t vbase = vs0 + (tile & 1) * KVBUF_BYTES + vfrag;
        const uint32_t vbase2 = vs0 + (tile & 1) * KVBUF_BYTES + vfrag2;

        // ---- S = Q @ K^T
        float sacc[8][4];
        #pragma unroll
        for (int nt = 0; nt < 8; nt++)
            #pragma unroll
            for (int jj = 0; jj < 4; jj++) sacc[nt][jj] = 0.0f;

        #pragma unroll
        for (int kc = 0; kc < 4; kc++) {
            #pragma unroll
            for (int np = 0; np < 4; np++) {
                uint32_t r0, r1, r2, r3;
                LDMX4(r0, r1, r2, r3, kbase + np * (16 * HSTR * 4) + kc * 32);
                mma16(sacc[2 * np],     qf[kc], r0, r1);
                mma16(sacc[2 * np + 1], qf[kc], r2, r3);
            }
        }

        // ---- online softmax max update (log2 domain), exp on MUFU
        float tm0 = -1e30f, tm1 = -1e30f;
        #pragma unroll
        for (int nt = 0; nt < 8; nt++) {
            tm0 = fmaxf(tm0, fmaxf(sacc[nt][0], sacc[nt][1]));
            tm1 = fmaxf(tm1, fmaxf(sacc[nt][2], sacc[nt][3]));
        }
        tm0 = fmaxf(tm0, __shfl_xor_sync(0xffffffff, tm0, 1));
        tm0 = fmaxf(tm0, __shfl_xor_sync(0xffffffff, tm0, 2));
        tm1 = fmaxf(tm1, __shfl_xor_sync(0xffffffff, tm1, 1));
        tm1 = fmaxf(tm1, __shfl_xor_sync(0xffffffff, tm1, 2));

        if (__any_sync(0xffffffff, (tm0 > m0) | (tm1 > m1))) {
            float mn0 = fmaxf(m0, tm0), mn1 = fmaxf(m1, tm1);
            float corr0 = ex2a(m0 - mn0), corr1 = ex2a(m1 - mn1);
            m0 = mn0; m1 = mn1;
            oex[0] *= corr0; oex[2] *= corr1;
            #pragma unroll
            for (int nt = 0; nt < 8; nt++) {
                o[nt][0] *= corr0; o[nt][1] *= corr0;
                o[nt][2] *= corr1; o[nt][3] *= corr1;
            }
        }

        #pragma unroll
        for (int nt = 0; nt < 8; nt++) {
            sacc[nt][0] = ex2a(sacc[nt][0] - m0);
            sacc[nt][1] = ex2a(sacc[nt][1] - m0);
            sacc[nt][2] = ex2a(sacc[nt][2] - m1);
            sacc[nt][3] = ex2a(sacc[nt][3] - m1);
        }

        // ---- O += P @ V (+ ones column -> l) via ldmatrix.trans
        #pragma unroll
        for (int kc = 0; kc < 4; kc++) {
            uint32_t af[4];
            af[0] = h2pack(sacc[2 * kc][0], sacc[2 * kc][1]);
            af[1] = h2pack(sacc[2 * kc][2], sacc[2 * kc][3]);
            af[2] = h2pack(sacc[2 * kc + 1][0], sacc[2 * kc + 1][1]);
            af[3] = h2pack(sacc[2 * kc + 1][2], sacc[2 * kc + 1][3]);
            #pragma unroll
            for (int np = 0; np < 4; np++) {
                uint32_t r0, r1, r2, r3;
                LDMX4T(r0, r1, r2, r3, vbase + kc * (16 * HSTR * 4) + np * 32);
                mma16(o[2 * np],     af, r0, r1);
                mma16(o[2 * np + 1], af, r2, r3);
            }
            {   // ones-column octet (n = 64..71): l accumulates in col 64
                uint32_t e0, e1;
                LDMX2T(e0, e1, vbase2 + kc * (16 * HSTR * 4));
                mma16(oex, af, e0, e1);
            }
        }
    }

    // ---- epilogue: l lives in ones-column (c==0 lane of each row group)
    const int src = lane & 28;   // lane (g<<2)|0
    const float l0 = __shfl_sync(0xffffffff, oex[0], src);
    const float l1 = __shfl_sync(0xffffffff, oex[2], src);
    const float inv0 = 1.0f / l0, inv1 = 1.0f / l1;
    uint32_t* ob = Og + (qrow0 + wid * 16 + g) * NP_ + h * 32;
    #pragma unroll
    for (int nt = 0; nt < 8; nt++) {
        ob[nt * 4 + c]            = h2pack(o[nt][0] * inv0, o[nt][1] * inv0);
        ob[8 * NP_ + nt * 4 + c]  = h2pack(o[nt][2] * inv1, o[nt][3] * inv1);
    }
}

// ---------------- launch ----------------
extern "C" void kernel_launch(void* const* d_in, const int* in_sizes, int n_in,
                              void* d_out, int out_size)
{
    const float* x  = (const float*)d_in[0];
    const float* Wq = (const float*)d_in[1];
    const float* bq = (const float*)d_in[2];
    const float* Wk = (const float*)d_in[3];
    const float* bk = (const float*)d_in[4];
    const float* Wv = (const float*)d_in[5];
    const float* bv = (const float*)d_in[6];
    const float* Wo = (const float*)d_in[7];
    const float* bo = (const float*)d_in[8];
    float* out = (float*)d_out;

    uint32_t *xh, *Qh, *Kh, *Vh, *Oh, *Whn;
    cudaGetSymbolAddress((void**)&xh, g_xh);
    cudaGetSymbolAddress((void**)&Qh, g_qh);
    cudaGetSymbolAddress((void**)&Kh, g_kh);
    cudaGetSymbolAddress((void**)&Vh, g_vh);
    cudaGetSymbolAddress((void**)&Oh, g_oh);
    cudaGetSymbolAddress((void**)&Whn, g_wh);

    cvt_x<<<2048, 256>>>((const float4*)x, (uint4*)xh);
    dim3 wgrid(NP_ / 32, D_ / 32, 4);   // (8, 16, 4)
    dim3 wblk(32, 8);
    cvt_wn<<<wgrid, wblk>>>(Wq, Wk, Wv, Wo, Whn);

    dim3 qkv_grid(D_ / 128, (B_ * S_) / 128, 3);   // (4, 64, 3)
    gemm_h_qkv<<<qkv_grid, 256>>>(xh, Whn, bq, Qh, bk, Kh, bv, Vh);

    dim3 agrid(S_ / AT_BM, H_, B_);  // (64, 8, 2) = 1024 blocks
    attn_h<<<agrid, 128>>>(Qh, Kh, Vh, Oh);

    dim3 ogrid(D_ / 128, (B_ * S_) / 128);         // (4, 64)
    gemm_h_out<<<ogrid, 256>>>(Oh, Whn, bo, out);
}

// round 14
// speedup vs baseline: 1.0341x; 1.0146x over previous
#include <cuda_runtime.h>
#include <cuda_fp16.h>
#include <cstddef>
#include <cstdint>

// Problem constants
#define B_ 2
#define S_ 4096
#define D_ 512
#define H_ 8
#define DH_ 64
#define NP_ 256   // pairs per row (D_/2)

// ---------------- scratch (no allocation allowed) ----------------
__device__ __align__(16) uint32_t g_xh[(size_t)B_ * S_ * NP_];
__device__ __align__(16) uint32_t g_qh[(size_t)B_ * S_ * NP_];
__device__ __align__(16) uint32_t g_kh[(size_t)B_ * S_ * NP_];
__device__ __align__(16) uint32_t g_vh[(size_t)B_ * S_ * NP_];
__device__ __align__(16) uint32_t g_oh[(size_t)B_ * S_ * NP_];
// weights TRANSPOSED, k-pair-packed half: [4][512 n][256 kp] uint32
__device__ __align__(16) uint32_t g_wh[4][(size_t)D_ * NP_];

// ---------------- helpers ----------------
__device__ __forceinline__ uint32_t smem_u32(const void* p) {
    uint32_t a;
    asm("{ .reg .u64 t; cvta.to.shared.u64 t, %1; cvt.u32.u64 %0, t; }"
        : "=r"(a) : "l"(p));
    return a;
}
__device__ __forceinline__ uint32_t h2pack(float lo, float hi) {
    __half2 h = __floats2half2_rn(lo, hi);
    return *(uint32_t*)&h;
}
__device__ __forceinline__ uint32_t hmul2u(uint32_t a, __half2 s) {
    __half2 r = __hmul2(*(__half2*)&a, s);
    return *(uint32_t*)&r;
}
// exp2 on the MUFU pipe: 1 issue slot, ~2 ulp.
__device__ __forceinline__ float ex2a(float x) {
    float y;
    asm("ex2.approx.ftz.f32 %0, %1;" : "=f"(y) : "f"(x));
    return y;
}
// cp.async: 16B global->shared, L1-bypass (cg)
__device__ __forceinline__ void cp16(uint32_t smem_dst, const void* gptr) {
    asm volatile("cp.async.cg.shared.global [%0], [%1], 16;"
                 :: "r"(smem_dst), "l"(gptr) : "memory");
}
#define CP_COMMIT() asm volatile("cp.async.commit_group;" ::: "memory")
#define CP_WAIT(N)  asm volatile("cp.async.wait_group %0;" :: "n"(N) : "memory")

// fp16 MMA: D(16x8) += A(16x16) * B(16x8), fp32 accum
__device__ __forceinline__ void mma16(float* d, const uint32_t* a,
                                      uint32_t b0, uint32_t b1) {
    asm volatile(
        "mma.sync.aligned.m16n8k16.row.col.f32.f16.f16.f32 "
        "{%0,%1,%2,%3}, {%4,%5,%6,%7}, {%8,%9}, {%0,%1,%2,%3};"
        : "+f"(d[0]), "+f"(d[1]), "+f"(d[2]), "+f"(d[3])
        : "r"(a[0]), "r"(a[1]), "r"(a[2]), "r"(a[3]), "r"(b0), "r"(b1));
}

#define LDMX4(r0, r1, r2, r3, addr)                                        \
    asm volatile("ldmatrix.sync.aligned.m8n8.x4.shared.b16 "               \
                 "{%0,%1,%2,%3}, [%4];"                                    \
                 : "=r"(r0), "=r"(r1), "=r"(r2), "=r"(r3) : "r"(addr))
#define LDMX4T(r0, r1, r2, r3, addr)                                       \
    asm volatile("ldmatrix.sync.aligned.m8n8.x4.trans.shared.b16 "         \
                 "{%0,%1,%2,%3}, [%4];"                                    \
                 : "=r"(r0), "=r"(r1), "=r"(r2), "=r"(r3) : "r"(addr))

// ================= x -> half pairs =================
__global__ void __launch_bounds__(256)
cvt_x(const float4* __restrict__ x, uint4* __restrict__ xh)
{
    size_t i = (size_t)blockIdx.x * 256 + threadIdx.x;
    float4 a = x[2 * i], b = x[2 * i + 1];
    uint4 o;
    o.x = h2pack(a.x, a.y); o.y = h2pack(a.z, a.w);
    o.z = h2pack(b.x, b.y); o.w = h2pack(b.z, b.w);
    xh[i] = o;
}

// ================= W -> transposed k-pair-packed half ======================
__global__ void __launch_bounds__(256)
cvt_wn(const float* __restrict__ Wq, const float* __restrict__ Wk,
       const float* __restrict__ Wv, const float* __restrict__ Wo,
       uint32_t* __restrict__ Whn)
{
    __shared__ uint32_t t[32][33];
    const float* W;
    if (blockIdx.z == 0)      W = Wq;
    else if (blockIdx.z == 1) W = Wk;
    else if (blockIdx.z == 2) W = Wv;
    else                      W = Wo;
    const int tx = threadIdx.x, ty = threadIdx.y;
    const int kp0 = blockIdx.x * 32, n0 = blockIdx.y * 32;
    #pragma unroll
    for (int i = 0; i < 4; i++) {
        int kp = kp0 + ty + i * 8;
        t[ty + i * 8][tx] = h2pack(W[(size_t)(2 * kp) * D_ + n0 + tx],
                                   W[(size_t)(2 * kp + 1) * D_ + n0 + tx]);
    }
    __syncthreads();
    uint32_t* dst = Whn + (size_t)blockIdx.z * D_ * NP_;
    #pragma unroll
    for (int i = 0; i < 4; i++) {
        int n = n0 + ty + i * 8;
        dst[(size_t)n * NP_ + kp0 + tx] = t[tx][ty + i * 8];
    }
}

// ================= fp16 GEMM: C = relu(Ah[M,512] @ W + b) ==================
#define GA_STR 20
#define GAB (128 * GA_STR)    // uint32 per A buffer (== W buffer)

template <int OUT_HALF>
__device__ __forceinline__ void gemm_h_body(
    const uint32_t* __restrict__ Ah_g,
    const uint32_t* __restrict__ Wn_g,
    const float* __restrict__ bias,
    void* __restrict__ Cout,
    int bm, int bn)
{
    __shared__ __align__(16) uint32_t Ah[2][GAB];
    __shared__ __align__(16) uint32_t Wn[2][GAB];

    const int tid = threadIdx.x;
    const int lane = tid & 31;
    const int wid = tid >> 5;
    const int wm = wid >> 2;
    const int wn = wid & 3;
    const int g = lane >> 2;
    const int c = lane & 3;

    const uint32_t ah0 = smem_u32(&Ah[0][0]);
    const uint32_t wn0 = smem_u32(&Wn[0][0]);

    const int j = lane >> 3, r = lane & 7;
    const uint32_t afrag = (((j & 1) * 8 + r) * GA_STR + (j >> 1) * 4) * 4;
    const uint32_t wfrag = (((j >> 1) * 8 + r) * GA_STR + (j & 1) * 4) * 4;

    float acc[4][4][4];
    #pragma unroll
    for (int mt = 0; mt < 4; mt++)
        #pragma unroll
        for (int nt = 0; nt < 4; nt++)
            #pragma unroll
            for (int jj = 0; jj < 4; jj++) acc[mt][nt][jj] = 0.0f;

    #pragma unroll
    for (int i = 0; i < 2; i++) {
        int cid = 2 * tid + i;
        int m = cid >> 2, ch = cid & 3;
        cp16(ah0 + (m * GA_STR + 4 * ch) * 4,
             Ah_g + (size_t)(bm + m) * NP_ + 4 * ch);
        cp16(wn0 + (m * GA_STR + 4 * ch) * 4,
             Wn_g + (size_t)(bn + m) * NP_ + 4 * ch);
    }
    CP_COMMIT();

    for (int kt = 0; kt < 16; kt++) {
        __syncthreads();
        if (kt < 15) {
            const int nb = (kt + 1) & 1;
            #pragma unroll
            for (int i = 0; i < 2; i++) {
                int cid = 2 * tid + i;
                int m = cid >> 2, ch = cid & 3;
                cp16(ah0 + (nb * GAB + m * GA_STR + 4 * ch) * 4,
                     Ah_g + (size_t)(bm + m) * NP_ + (kt + 1) * 16 + 4 * ch);
                cp16(wn0 + (nb * GAB + m * GA_STR + 4 * ch) * 4,
                     Wn_g + (size_t)(bn + m) * NP_ + (kt + 1) * 16 + 4 * ch);
            }
            CP_COMMIT();
            CP_WAIT(1);
        } else {
            CP_WAIT(0);
        }
        __syncthreads();

        const uint32_t a_ld = ah0 + (kt & 1) * (GAB * 4) + afrag;
        const uint32_t w_ld = wn0 + (kt & 1) * (GAB * 4) + wfrag;

        #pragma unroll
        for (int kc = 0; kc < 2; kc++) {
            uint32_t af[4][4];
            #pragma unroll
            for (int mt = 0; mt < 4; mt++)
                LDMX4(af[mt][0], af[mt][1], af[mt][2], af[mt][3],
                      a_ld + (wm * 64 + mt * 16) * (GA_STR * 4) + kc * 32);
            #pragma unroll
            for (int ntb = 0; ntb < 2; ntb++) {
                uint32_t b0, b1, b2, b3;
                LDMX4(b0, b1, b2, b3,
                      w_ld + (wn * 32 + ntb * 16) * (GA_STR * 4) + kc * 32);
                #pragma unroll
                for (int mt = 0; mt < 4; mt++) {
                    mma16(acc[mt][2 * ntb],     af[mt], b0, b1);
                    mma16(acc[mt][2 * ntb + 1], af[mt], b2, b3);
                }
            }
        }
    }

    #pragma unroll
    for (int mt = 0; mt < 4; mt++) {
        const int row = bm + wm * 64 + mt * 16 + g;
        #pragma unroll
        for (int nt = 0; nt < 4; nt++) {
            const int col = bn + wn * 32 + nt * 8 + 2 * c;
            const float b0 = bias[col], b1 = bias[col + 1];
            float v00 = fmaxf(acc[mt][nt][0] + b0, 0.0f);
            float v01 = fmaxf(acc[mt][nt][1] + b1, 0.0f);
            float v10 = fmaxf(acc[mt][nt][2] + b0, 0.0f);
            float v11 = fmaxf(acc[mt][nt][3] + b1, 0.0f);
            if (OUT_HALF) {
                uint32_t* Ch = (uint32_t*)Cout;
                Ch[(size_t)row * NP_ + (col >> 1)]       = h2pack(v00, v01);
                Ch[(size_t)(row + 8) * NP_ + (col >> 1)] = h2pack(v10, v11);
            } else {
                float* Cf = (float*)Cout;
                float2 a; a.x = v00; a.y = v01;
                float2 bb; bb.x = v10; bb.y = v11;
                *(float2*)(Cf + (size_t)row * D_ + col) = a;
                *(float2*)(Cf + (size_t)(row + 8) * D_ + col) = bb;
            }
        }
    }
}

__global__ void __launch_bounds__(256, 2)
gemm_h_qkv(const uint32_t* __restrict__ xh, const uint32_t* __restrict__ Whn,
           const float* __restrict__ bq, uint32_t* __restrict__ Q,
           const float* __restrict__ bk, uint32_t* __restrict__ K,
           const float* __restrict__ bv, uint32_t* __restrict__ V)
{
    const float* bias; uint32_t* C;
    if (blockIdx.z == 0)      { bias = bq; C = Q; }
    else if (blockIdx.z == 1) { bias = bk; C = K; }
    else                      { bias = bv; C = V; }
    gemm_h_body<1>(xh, Whn + (size_t)blockIdx.z * D_ * NP_, bias, C,
                   blockIdx.y * 128, blockIdx.x * 128);
}

__global__ void __launch_bounds__(256, 2)
gemm_h_out(const uint32_t* __restrict__ Ah, const uint32_t* __restrict__ Whn,
           const float* __restrict__ bias, float* __restrict__ C)
{
    gemm_h_body<0>(Ah, Whn + (size_t)3 * D_ * NP_, bias, C,
                   blockIdx.y * 128, blockIdx.x * 128);
}

// ================= flash attention: triple-buffer, 1 sync/tile ==============
// BM=64 q rows, BN=64 keys/tile, 128 threads (4 warps, 16m x 64n each).
// K/V in 3 rotating smem buffers (cp.async, 2 groups in flight).
// Q staged into buffer 2's space (dead after register extraction).
// Softmax denominator via CONSTANT ones B-fragment (no smem, no ldmatrix).
#define AT_BM 64
#define HSTR 36
#define KVW  (64 * HSTR)            // uint32 per K (or V) matrix
#define TBW  (2 * KVW)              // uint32 per tile buffer (K then V)
#define TBB  (TBW * 4)              // bytes per tile buffer: 18432
#define ATTN_SMEM (3 * TBB)         // 55296 B

__global__ void __launch_bounds__(128, 4)
attn_h(const uint32_t* __restrict__ Qg, const uint32_t* __restrict__ Kg,
       const uint32_t* __restrict__ Vg, uint32_t* __restrict__ Og)
{
    extern __shared__ __align__(16) uint32_t smn[];
    const uint32_t sbase = smem_u32(smn);

    const int tid = threadIdx.x;
    const int lane = tid & 31;
    const int wid = tid >> 5;
    const int g = lane >> 2;   // 0..7
    const int c = lane & 3;    // 0..3
    const int qblk = blockIdx.x;
    const int h = blockIdx.y;
    const int b = blockIdx.z;

    const __half2 sc2 = __float2half2_rn(0.18033688f);  // (1/8)*log2(e)

    const size_t kvrow0 = (size_t)b * S_;
    const int sn0 = tid >> 3;        // key row (0..15) for it=0
    const int sch = tid & 7;         // 16B chunk within row

    // ---- prologue: cp tile 0 -> buf0, tile 1 -> buf1 (two groups)
    #pragma unroll
    for (int it = 0; it < 4; it++) {
        int n = sn0 + it * 16;
        size_t goff = (kvrow0 + n) * NP_ + h * 32 + 4 * sch;
        uint32_t so = (uint32_t)((n * HSTR + 4 * sch) * 4);
        cp16(sbase + so, Kg + goff);
        cp16(sbase + KVW * 4 + so, Vg + goff);
    }
    CP_COMMIT();
    #pragma unroll
    for (int it = 0; it < 4; it++) {
        int n = sn0 + it * 16;
        size_t goff = (kvrow0 + 64 + n) * NP_ + h * 32 + 4 * sch;
        uint32_t so = (uint32_t)(TBB + (n * HSTR + 4 * sch) * 4);
        cp16(sbase + so, Kg + goff);
        cp16(sbase + KVW * 4 + so, Vg + goff);
    }
    CP_COMMIT();

    // ---- stage Q into buffer 2's space (scaled)
    uint32_t* Qs = smn + 2 * TBW;
    const size_t qrow0 = (size_t)b * S_ + qblk * AT_BM;
    #pragma unroll
    for (int it = 0; it < 4; it++) {
        int idx = tid + it * 128;
        int m = idx >> 3, ch = idx & 7;
        uint4 u = *(const uint4*)(Qg + (qrow0 + m) * NP_ + h * 32 + 4 * ch);
        u.x = hmul2u(u.x, sc2); u.y = hmul2u(u.y, sc2);
        u.z = hmul2u(u.z, sc2); u.w = hmul2u(u.w, sc2);
        *(uint4*)&Qs[m * HSTR + 4 * ch] = u;
    }
    __syncthreads();

    // Q a-frags to registers (4 k-chunks of 16 d)
    uint32_t qf[4][4];
    {
        const int r0 = (wid * 16 + g) * HSTR;
        const int r1 = r0 + 8 * HSTR;
        #pragma unroll
        for (int kc = 0; kc < 4; kc++) {
            qf[kc][0] = Qs[r0 + 8 * kc + c];
            qf[kc][1] = Qs[r1 + 8 * kc + c];
            qf[kc][2] = Qs[r0 + 8 * kc + 4 + c];
            qf[kc][3] = Qs[r1 + 8 * kc + 4 + c];
        }
    }

    // ldmatrix per-thread fragment offsets (within a tile buffer)
    const int j = lane >> 3, r = lane & 7;
    const uint32_t kfrag = ((((j >> 1) * 8 + r) * HSTR + (j & 1) * 4) << 2);
    const uint32_t vfrag = (uint32_t)(KVW * 4) +
                           ((((j & 1) * 8 + r) * HSTR + (j >> 1) * 4) << 2);
    // constant ones B-fragment: B[k][0]=1 for all k -> lanes 0-3 hold (1,1)
    const uint32_t onesb = (lane < 4) ? 0x3C003C00u : 0u;

    float o[8][4];
    #pragma unroll
    for (int nt = 0; nt < 8; nt++)
        #pragma unroll
        for (int jj = 0; jj < 4; jj++) o[nt][jj] = 0.0f;
    float oex[4] = {0.0f, 0.0f, 0.0f, 0.0f};   // l accumulates in col 0
    float m0 = -1e30f, m1 = -1e30f;

    // rotating buffer bases: cur (tile t), nxt (t+1), tgt (t+2 cp target)
    uint32_t bcur = sbase, bnxt = sbase + TBB, btgt = sbase + 2 * TBB;

    const int NTILES = S_ / 64;
    for (int tile = 0; tile < NTILES; tile++) {
        if (tile < NTILES - 1) { CP_WAIT(1); } else { CP_WAIT(0); }
        __syncthreads();   // tile's data visible; all reads of btgt done

        if (tile + 2 < NTILES) {
            const int t2 = (tile + 2) * 64;
            #pragma unroll
            for (int it = 0; it < 4; it++) {
                int n = sn0 + it * 16;
                size_t goff = (kvrow0 + t2 + n) * NP_ + h * 32 + 4 * sch;
                uint32_t so = (uint32_t)((n * HSTR + 4 * sch) * 4);
                cp16(btgt + so, Kg + goff);
                cp16(btgt + KVW * 4 + so, Vg + goff);
            }
            CP_COMMIT();
        }

        const uint32_t kbase = bcur + kfrag;
        const uint32_t vbase = bcur + vfrag;

        // ---- S = Q @ K^T
        float sacc[8][4];
        #pragma unroll
        for (int nt = 0; nt < 8; nt++)
            #pragma unroll
            for (int jj = 0; jj < 4; jj++) sacc[nt][jj] = 0.0f;

        #pragma unroll
        for (int kc = 0; kc < 4; kc++) {
            #pragma unroll
            for (int np = 0; np < 4; np++) {
                uint32_t r0, r1, r2, r3;
                LDMX4(r0, r1, r2, r3, kbase + np * (16 * HSTR * 4) + kc * 32);
                mma16(sacc[2 * np],     qf[kc], r0, r1);
                mma16(sacc[2 * np + 1], qf[kc], r2, r3);
            }
        }

        // ---- online softmax max update (log2 domain), exp on MUFU
        float tm0 = -1e30f, tm1 = -1e30f;
        #pragma unroll
        for (int nt = 0; nt < 8; nt++) {
            tm0 = fmaxf(tm0, fmaxf(sacc[nt][0], sacc[nt][1]));
            tm1 = fmaxf(tm1, fmaxf(sacc[nt][2], sacc[nt][3]));
        }
        tm0 = fmaxf(tm0, __shfl_xor_sync(0xffffffff, tm0, 1));
        tm0 = fmaxf(tm0, __shfl_xor_sync(0xffffffff, tm0, 2));
        tm1 = fmaxf(tm1, __shfl_xor_sync(0xffffffff, tm1, 1));
        tm1 = fmaxf(tm1, __shfl_xor_sync(0xffffffff, tm1, 2));

        if (__any_sync(0xffffffff, (tm0 > m0) | (tm1 > m1))) {
            float mn0 = fmaxf(m0, tm0), mn1 = fmaxf(m1, tm1);
            float corr0 = ex2a(m0 - mn0), corr1 = ex2a(m1 - mn1);
            m0 = mn0; m1 = mn1;
            oex[0] *= corr0; oex[2] *= corr1;
            #pragma unroll
            for (int nt = 0; nt < 8; nt++) {
                o[nt][0] *= corr0; o[nt][1] *= corr0;
                o[nt][2] *= corr1; o[nt][3] *= corr1;
            }
        }

        #pragma unroll
        for (int nt = 0; nt < 8; nt++) {
            sacc[nt][0] = ex2a(sacc[nt][0] - m0);
            sacc[nt][1] = ex2a(sacc[nt][1] - m0);
            sacc[nt][2] = ex2a(sacc[nt][2] - m1);
            sacc[nt][3] = ex2a(sacc[nt][3] - m1);
        }

        // ---- O += P @ V, l += P @ ones (constant B-frag)
        #pragma unroll
        for (int kc = 0; kc < 4; kc++) {
            uint32_t af[4];
            af[0] = h2pack(sacc[2 * kc][0], sacc[2 * kc][1]);
            af[1] = h2pack(sacc[2 * kc][2], sacc[2 * kc][3]);
            af[2] = h2pack(sacc[2 * kc + 1][0], sacc[2 * kc + 1][1]);
            af[3] = h2pack(sacc[2 * kc + 1][2], sacc[2 * kc + 1][3]);
            #pragma unroll
            for (int np = 0; np < 4; np++) {
                uint32_t r0, r1, r2, r3;
                LDMX4T(r0, r1, r2, r3, vbase + kc * (16 * HSTR * 4) + np * 32);
                mma16(o[2 * np],     af, r0, r1);
                mma16(o[2 * np + 1], af, r2, r3);
            }
            mma16(oex, af, onesb, onesb);
        }

        // rotate buffers
        uint32_t t = bcur; bcur = bnxt; bnxt = btgt; btgt = t;
    }

    // ---- epilogue: l lives in ones-column output (c==0 lane of each quad)
    const int src = lane & 28;
    const float l0 = __shfl_sync(0xffffffff, oex[0], src);
    const float l1 = __shfl_sync(0xffffffff, oex[2], src);
    const float inv0 = 1.0f / l0, inv1 = 1.0f / l1;
    uint32_t* ob = Og + (qrow0 + wid * 16 + g) * NP_ + h * 32;
    #pragma unroll
    for (int nt = 0; nt < 8; nt++) {
        ob[nt * 4 + c]            = h2pack(o[nt][0] * inv0, o[nt][1] * inv0);
        ob[8 * NP_ + nt * 4 + c]  = h2pack(o[nt][2] * inv1, o[nt][3] * inv1);
    }
}

// ---------------- launch ----------------
extern "C" void kernel_launch(void* const* d_in, const int* in_sizes, int n_in,
                              void* d_out, int out_size)
{
    const float* x  = (const float*)d_in[0];
    const float* Wq = (const float*)d_in[1];
    const float* bq = (const float*)d_in[2];
    const float* Wk = (const float*)d_in[3];
    const float* bk = (const float*)d_in[4];
    const float* Wv = (const float*)d_in[5];
    const float* bv = (const float*)d_in[6];
    const float* Wo = (const float*)d_in[7];
    const float* bo = (const float*)d_in[8];
    float* out = (float*)d_out;

    uint32_t *xh, *Qh, *Kh, *Vh, *Oh, *Whn;
    cudaGetSymbolAddress((void**)&xh, g_xh);
    cudaGetSymbolAddress((void**)&Qh, g_qh);
    cudaGetSymbolAddress((void**)&Kh, g_kh);
    cudaGetSymbolAddress((void**)&Vh, g_vh);
    cudaGetSymbolAddress((void**)&Oh, g_oh);
    cudaGetSymbolAddress((void**)&Whn, g_wh);

    cvt_x<<<2048, 256>>>((const float4*)x, (uint4*)xh);
    dim3 wgrid(NP_ / 32, D_ / 32, 4);   // (8, 16, 4)
    dim3 wblk(32, 8);
    cvt_wn<<<wgrid, wblk>>>(Wq, Wk, Wv, Wo, Whn);

    dim3 qkv_grid(D_ / 128, (B_ * S_) / 128, 3);   // (4, 64, 3)
    gemm_h_qkv<<<qkv_grid, 256>>>(xh, Whn, bq, Qh, bk, Kh, bv, Vh);

    cudaFuncSetAttribute(attn_h, cudaFuncAttributeMaxDynamicSharedMemorySize,
                         ATTN_SMEM);
    dim3 agrid(S_ / AT_BM, H_, B_);  // (64, 8, 2) = 1024 blocks
    attn_h<<<agrid, 128, ATTN_SMEM>>>(Qh, Kh, Vh, Oh);

    dim3 ogrid(D_ / 128, (B_ * S_) / 128);         // (4, 64)
    gemm_h_out<<<ogrid, 256>>>(Oh, Whn, bo, out);
}